// round 16
// baseline (speedup 1.0000x reference)
#include <cuda_runtime.h>
#include <cuda_fp16.h>
#include <math.h>
#include <stdint.h>

// Shapes fixed by the problem: N=8192, D=512, 3 classes
#define NMAX 8192
#define DMAX 512
#define NTILE 64   // N / 128

// ---------------- device scratch (static, no runtime allocation) ------------
__device__ __half g_fh[(size_t)NMAX * DMAX];   // normalized features, ORIGINAL order
__device__ __half g_S[(size_t)NMAX * NMAX];    // scaled logits (sorted coords), fp16
__device__ float  g_negpart[(size_t)NMAX * 64];// per-(sorted row, col-tile) exp partials
__device__ int    g_perm[NMAX];                // sorted -> original index
__device__ int    g_bnd[4];                    // {0, b1, b2, NV}
__device__ float  g_rowloss[NMAX];
__device__ int    g_rowflag[NMAX];

// ---------------- helpers ----------------------------------------------------
__device__ __forceinline__ float wred_f(float x) {
#pragma unroll
    for (int o = 16; o; o >>= 1) x += __shfl_xor_sync(0xffffffffu, x, o);
    return x;
}
__device__ __forceinline__ int wred_i(int x) {
#pragma unroll
    for (int o = 16; o; o >>= 1) x += __shfl_xor_sync(0xffffffffu, x, o);
    return x;
}
// softplus: exact 2-MUFU path for |d|<4, 1-MUFU quadratic for |d|>=4
__device__ __forceinline__ float softplus_fast(float d) {
    const float ad = fabsf(d);
    const float e  = __expf(-ad);
    const float base = fmaxf(d, 0.f);
    if (ad >= 4.f) {
        return base + e * (1.f - 0.5f * e);
    }
    return base + __logf(1.f + e);
}
__device__ __forceinline__ int clsof(int x, int b1, int b2, int NV) {
    return (x < b1) ? 0 : (x < b2) ? 1 : (x < NV) ? 2 : 3;
}

__device__ __forceinline__ void mma_f16(float* d, const uint32_t* a, const uint32_t* b) {
    asm volatile(
        "mma.sync.aligned.m16n8k16.row.col.f32.f16.f16.f32 "
        "{%0,%1,%2,%3}, {%4,%5,%6,%7}, {%8,%9}, {%0,%1,%2,%3};"
        : "+f"(d[0]), "+f"(d[1]), "+f"(d[2]), "+f"(d[3])
        : "r"(a[0]), "r"(a[1]), "r"(a[2]), "r"(a[3]),
          "r"(b[0]), "r"(b[1]));
}
__device__ __forceinline__ void ldsm_x4(uint32_t* r, uint32_t a) {
    asm volatile("ldmatrix.sync.aligned.m8n8.x4.shared.b16 {%0,%1,%2,%3}, [%4];"
                 : "=r"(r[0]), "=r"(r[1]), "=r"(r[2]), "=r"(r[3]) : "r"(a));
}
__device__ __forceinline__ void ldsm_x2(uint32_t* r, uint32_t a) {
    asm volatile("ldmatrix.sync.aligned.m8n8.x2.shared.b16 {%0,%1}, [%2];"
                 : "=r"(r[0]), "=r"(r[1]) : "r"(a));
}
__device__ __forceinline__ void cp_async16(uint32_t dst, const void* src) {
    size_t g = __cvta_generic_to_global(src);
    asm volatile("cp.async.cg.shared.global [%0], [%1], 16;"
                 :: "r"(dst), "l"(g) : "memory");
}

// ---------------- kernel 0: fused sort (block 0) + normalize (blocks 1..) ---
// Block 0: stable counting sort -> g_perm, g_bnd.
// Blocks 1..N/32: one WARP per row (4 float4 loads/lane = MLP 4, no syncs).
__global__ void __launch_bounds__(1024) k_prep(
    const float* __restrict__ feats,
    const int* __restrict__ labels,
    const int* __restrict__ bad,
    int N, int D)
{
    const int t = threadIdx.x;

    if (blockIdx.x == 0) {
        __shared__ uint32_t wt01[32], wt23[32];
        const int lane = t & 31;
        const int wid = t >> 5;

        const int4* lab4 = reinterpret_cast<const int4*>(labels);
        const int4* bad4 = reinterpret_cast<const int4*>(bad);
        int4 l0 = lab4[t * 2], l1 = lab4[t * 2 + 1];
        int4 d0 = bad4[t * 2], d1 = bad4[t * 2 + 1];

        int code[8];
        code[0] = (d0.x == 0) ? l0.x : 3;
        code[1] = (d0.y == 0) ? l0.y : 3;
        code[2] = (d0.z == 0) ? l0.z : 3;
        code[3] = (d0.w == 0) ? l0.w : 3;
        code[4] = (d1.x == 0) ? l1.x : 3;
        code[5] = (d1.y == 0) ? l1.y : 3;
        code[6] = (d1.z == 0) ? l1.z : 3;
        code[7] = (d1.w == 0) ? l1.w : 3;

        int cnt[4] = {0, 0, 0, 0};
#pragma unroll
        for (int e = 0; e < 8; e++) cnt[code[e]]++;

        uint32_t v01 = (uint32_t)cnt[0] | ((uint32_t)cnt[1] << 16);
        uint32_t v23 = (uint32_t)cnt[2] | ((uint32_t)cnt[3] << 16);
        uint32_t s01 = v01, s23 = v23;
#pragma unroll
        for (int off = 1; off < 32; off <<= 1) {
            uint32_t t1 = __shfl_up_sync(0xffffffffu, s01, off);
            uint32_t t2 = __shfl_up_sync(0xffffffffu, s23, off);
            if (lane >= off) { s01 += t1; s23 += t2; }
        }
        if (lane == 31) { wt01[wid] = s01; wt23[wid] = s23; }
        __syncthreads();
        if (wid == 0) {
            uint32_t w1 = wt01[lane], w2 = wt23[lane];
#pragma unroll
            for (int off = 1; off < 32; off <<= 1) {
                uint32_t t1 = __shfl_up_sync(0xffffffffu, w1, off);
                uint32_t t2 = __shfl_up_sync(0xffffffffu, w2, off);
                if (lane >= off) { w1 += t1; w2 += t2; }
            }
            wt01[lane] = w1; wt23[lane] = w2;
        }
        __syncthreads();

        const uint32_t wp01 = wid ? wt01[wid - 1] : 0u;
        const uint32_t wp23 = wid ? wt23[wid - 1] : 0u;
        const uint32_t tt01 = wt01[31], tt23 = wt23[31];

        const uint32_t ep01 = wp01 + s01 - v01;
        const uint32_t ep23 = wp23 + s23 - v23;
        int pre[4] = { (int)(ep01 & 0xffffu), (int)(ep01 >> 16),
                       (int)(ep23 & 0xffffu), (int)(ep23 >> 16) };
        const int tot0 = (int)(tt01 & 0xffffu);
        const int tot1 = (int)(tt01 >> 16);
        const int tot2 = (int)(tt23 & 0xffffu);
        int base[4] = { 0, tot0, tot0 + tot1, tot0 + tot1 + tot2 };

        int r[4] = {0, 0, 0, 0};
#pragma unroll
        for (int e = 0; e < 8; e++) {
            const int j = t * 8 + e;
            const int c = code[e];
            g_perm[base[c] + pre[c] + r[c]] = j;
            r[c]++;
        }
        if (t == 0) {
            g_bnd[0] = 0;
            g_bnd[1] = base[1];
            g_bnd[2] = base[2];
            g_bnd[3] = base[3];
        }
    } else {
        // normalize: one warp per row, 32 rows per block
        const int lane = t & 31;
        const int warp = t >> 5;
        const int row = (blockIdx.x - 1) * 32 + warp;

        const float4* src = reinterpret_cast<const float4*>(feats + (size_t)row * D);
        float4 v[4];
#pragma unroll
        for (int q = 0; q < 4; q++) v[q] = src[lane + 32 * q];

        float ss = 0.f;
#pragma unroll
        for (int q = 0; q < 4; q++)
            ss += v[q].x * v[q].x + v[q].y * v[q].y + v[q].z * v[q].z + v[q].w * v[q].w;
        ss = wred_f(ss);
        const float rinv = rsqrtf(ss);

        uint2* dst = reinterpret_cast<uint2*>(g_fh + (size_t)row * D);
#pragma unroll
        for (int q = 0; q < 4; q++) {
            uint2 o;
            __half2 h0 = __floats2half2_rn(v[q].x * rinv, v[q].y * rinv);
            __half2 h1 = __floats2half2_rn(v[q].z * rinv, v[q].w * rinv);
            o.x = *reinterpret_cast<uint32_t*>(&h0);
            o.y = *reinterpret_cast<uint32_t*>(&h1);
            dst[lane + 32 * q] = o;
        }
    }
}

// ---------------- kernel 2: fp16 GEMM, 128x128, 3-stage, perm-gathered ------
#define TCB 256
#define SM_STAGE 16384
#define SM_A(s) ((s) * SM_STAGE)
#define SM_B(s) (49152 + (s) * SM_STAGE)
#define SM_DYN 98304

__global__ void __launch_bounds__(TCB, 2) k_gemm_f16(int N, int D)
{
    extern __shared__ __align__(16) unsigned char dsm[];
    const uint32_t sbase = (uint32_t)__cvta_generic_to_shared(dsm);

    int t = blockIdx.x;
    int by = 0;
    {
        int rem = t;
        while (rem >= NTILE - by) { rem -= NTILE - by; by++; }
        t = rem;
    }
    const int bx = by + t;

    const int b1 = g_bnd[1];
    const int b2 = g_bnd[2];
    const int NV = g_bnd[3];
    const int ntv = (NV + 127) >> 7;
    if (bx >= ntv) return;

    const int row0 = by * 128;
    const int col0 = bx * 128;

    const int tid  = threadIdx.x;
    const int lane = tid & 31;
    const int warp = tid >> 5;
    const int wm   = warp >> 2;
    const int wn   = warp & 3;

    int cp_r[4], cp_sw[4], cp_g[4];
#pragma unroll
    for (int i = 0; i < 4; i++) {
        const int e = tid + i * TCB;
        cp_r[i]  = e >> 3;
        cp_g[i]  = e & 7;
        cp_sw[i] = cp_r[i] * 128 + ((cp_g[i] * 16) ^ ((cp_r[i] & 7) << 4));
    }

    const __half* __restrict__ fh = g_fh;
    const int* __restrict__ perm = g_perm;
    size_t prA[4], prB[4];
#pragma unroll
    for (int i = 0; i < 4; i++) {
        prA[i] = (size_t)perm[row0 + cp_r[i]] * D;
        prB[i] = (size_t)perm[col0 + cp_r[i]] * D;
    }

    float acc[4][4][4];
#pragma unroll
    for (int a = 0; a < 4; a++)
#pragma unroll
        for (int b = 0; b < 4; b++)
#pragma unroll
            for (int c = 0; c < 4; c++) acc[a][b][c] = 0.f;

    const int rr = lane & 7;
    const int xr = rr << 4;
    const int qa = lane >> 3;
    const int kA = (qa >> 1) << 4;
    const int kB = ((lane >> 3) & 1) << 4;
    int rowA[4], rowB[4];
#pragma unroll
    for (int mt = 0; mt < 4; mt++)
        rowA[mt] = ((wm << 6) + (mt << 4) + ((qa & 1) << 3) + rr) * 128;
#pragma unroll
    for (int nt = 0; nt < 4; nt++)
        rowB[nt] = ((wn << 5) + (nt << 3) + rr) * 128;

    const int NCH = D >> 6;

#pragma unroll
    for (int pc = 0; pc < 2; pc++) {
        const int koff = pc << 6;
#pragma unroll
        for (int i = 0; i < 4; i++) {
            cp_async16(sbase + SM_A(pc) + cp_sw[i], fh + prA[i] + koff + cp_g[i] * 8);
            cp_async16(sbase + SM_B(pc) + cp_sw[i], fh + prB[i] + koff + cp_g[i] * 8);
        }
        asm volatile("cp.async.commit_group;" ::: "memory");
    }

    for (int c = 0; c < NCH; c++) {
        const int buf = c % 3;
        if (c + 2 < NCH) {
            const int koff = (c + 2) << 6;
            const int nb = (c + 2) % 3;
#pragma unroll
            for (int i = 0; i < 4; i++) {
                cp_async16(sbase + SM_A(nb) + cp_sw[i], fh + prA[i] + koff + cp_g[i] * 8);
                cp_async16(sbase + SM_B(nb) + cp_sw[i], fh + prB[i] + koff + cp_g[i] * 8);
            }
            asm volatile("cp.async.commit_group;" ::: "memory");
            asm volatile("cp.async.wait_group 2;" ::: "memory");
        } else if (c + 1 < NCH) {
            asm volatile("cp.async.wait_group 1;" ::: "memory");
        } else {
            asm volatile("cp.async.wait_group 0;" ::: "memory");
        }
        __syncthreads();

        const uint32_t ab = sbase + SM_A(buf);
        const uint32_t bb = sbase + SM_B(buf);
#pragma unroll
        for (int ks = 0; ks < 4; ks++) {
            const int kk = ks << 5;
            uint32_t Af[4][4], Bf[4][2];
#pragma unroll
            for (int mt = 0; mt < 4; mt++)
                ldsm_x4(Af[mt], ab + rowA[mt] + ((kk + kA) ^ xr));
#pragma unroll
            for (int nt = 0; nt < 4; nt++)
                ldsm_x2(Bf[nt], bb + rowB[nt] + ((kk + kB) ^ xr));
#pragma unroll
            for (int mt = 0; mt < 4; mt++)
#pragma unroll
                for (int nt = 0; nt < 4; nt++)
                    mma_f16(acc[mt][nt], Af[mt], Bf[nt]);
        }
        __syncthreads();
    }

    // ---- epilogue ----
    float* SRow = reinterpret_cast<float*>(dsm);           // [128][4]
    float* SCol = reinterpret_cast<float*>(dsm + 2048);    // [128][2]
    __half* Tsm = reinterpret_cast<__half*>(dsm);          // reuse

    const float invT = 10.f;
    const int g  = lane >> 2;
    const int tq = lane & 3;

    bool storeT;
    {
        const int r0 = row0, r1 = row0 + 128, c0 = col0, c1 = col0 + 128;
        storeT = (r0 < b1 && c0 < b1)
              || (r0 < b2 && r1 > b1 && c0 < b2 && c1 > b1)
              || (r1 > b2 && c1 > b2 && row0 < NV && col0 < NV);
    }
    const bool allsame =
        (clsof(row0, b1, b2, NV) == clsof(row0 + 127, b1, b2, NV)) &&
        (clsof(col0, b1, b2, NV) == clsof(col0 + 127, b1, b2, NV)) &&
        (clsof(row0, b1, b2, NV) == clsof(col0, b1, b2, NV)) &&
        (clsof(row0, b1, b2, NV) != 3);

    if (storeT) {
        __half* __restrict__ S = g_S;
#pragma unroll
        for (int mt = 0; mt < 4; mt++) {
            const int row = row0 + (wm << 6) + (mt << 4) + g;
#pragma unroll
            for (int nt = 0; nt < 4; nt++) {
                const int col = col0 + (wn << 5) + (nt << 3) + (tq << 1);
                __half2 lo = __floats2half2_rn(acc[mt][nt][0] * invT, acc[mt][nt][1] * invT);
                __half2 hi = __floats2half2_rn(acc[mt][nt][2] * invT, acc[mt][nt][3] * invT);
                *reinterpret_cast<__half2*>(&S[(size_t)row * N + col]) = lo;
                *reinterpret_cast<__half2*>(&S[(size_t)(row + 8) * N + col]) = hi;
            }
        }
    }

    float rsum[8] = {0, 0, 0, 0, 0, 0, 0, 0};
    float csum[8] = {0, 0, 0, 0, 0, 0, 0, 0};
    if (!allsame) {
        int rcls[8], ccls[8];
#pragma unroll
        for (int mt = 0; mt < 4; mt++)
#pragma unroll
            for (int h = 0; h < 2; h++) {
                const int r = row0 + (wm << 6) + (mt << 4) + g + 8 * h;
                rcls[mt * 2 + h] = clsof(r, b1, b2, NV);
            }
#pragma unroll
        for (int nt = 0; nt < 4; nt++)
#pragma unroll
            for (int c = 0; c < 2; c++) {
                const int cc = col0 + (wn << 5) + (nt << 3) + (tq << 1) + c;
                ccls[nt * 2 + c] = clsof(cc, b1, b2, NV);
            }
#pragma unroll
        for (int mt = 0; mt < 4; mt++)
#pragma unroll
            for (int h = 0; h < 2; h++) {
                const int rc = rcls[mt * 2 + h];
#pragma unroll
                for (int nt = 0; nt < 4; nt++)
#pragma unroll
                    for (int c = 0; c < 2; c++) {
                        const int cc = ccls[nt * 2 + c];
                        const float s = acc[mt][nt][2 * h + c] * invT;
                        const float e = __expf(s - 10.f);
                        const bool m = (rc != cc) && (rc != 3) && (cc != 3);
                        const float ev = m ? e : 0.f;
                        rsum[mt * 2 + h] += ev;
                        csum[nt * 2 + c] += ev;
                    }
            }
#pragma unroll
        for (int k = 0; k < 8; k++) {
            rsum[k] += __shfl_xor_sync(0xffffffffu, rsum[k], 1);
            rsum[k] += __shfl_xor_sync(0xffffffffu, rsum[k], 2);
            csum[k] += __shfl_xor_sync(0xffffffffu, csum[k], 4);
            csum[k] += __shfl_xor_sync(0xffffffffu, csum[k], 8);
            csum[k] += __shfl_xor_sync(0xffffffffu, csum[k], 16);
        }
    }
    if (tq == 0) {
#pragma unroll
        for (int mt = 0; mt < 4; mt++)
#pragma unroll
            for (int h = 0; h < 2; h++) {
                const int rl = (wm << 6) + (mt << 4) + g + 8 * h;
                SRow[rl * 4 + wn] = rsum[mt * 2 + h];
            }
    }
    if (g == 0) {
#pragma unroll
        for (int nt = 0; nt < 4; nt++)
#pragma unroll
            for (int c = 0; c < 2; c++) {
                const int cl = (wn << 5) + (nt << 3) + (tq << 1) + c;
                SCol[cl * 2 + wm] = csum[nt * 2 + c];
            }
    }
    __syncthreads();

    if (tid < 128) {
        const float rp = SRow[tid * 4 + 0] + SRow[tid * 4 + 1]
                       + SRow[tid * 4 + 2] + SRow[tid * 4 + 3];
        g_negpart[(size_t)(row0 + tid) * 64 + bx] = rp;
    } else if (bx != by) {
        const int c = tid - 128;
        const float cp = SCol[c * 2 + 0] + SCol[c * 2 + 1];
        g_negpart[(size_t)(col0 + c) * 64 + by] = cp;
    }

    if (storeT && bx != by) {
        __syncthreads();
#pragma unroll
        for (int mt = 0; mt < 4; mt++) {
            const int r = (wm << 6) + (mt << 4) + g;
#pragma unroll
            for (int nt = 0; nt < 4; nt++) {
                const int c = (wn << 5) + (nt << 3) + (tq << 1);
                Tsm[(c) * 136 + r]         = __float2half_rn(acc[mt][nt][0] * invT);
                Tsm[(c + 1) * 136 + r]     = __float2half_rn(acc[mt][nt][1] * invT);
                Tsm[(c) * 136 + r + 8]     = __float2half_rn(acc[mt][nt][2] * invT);
                Tsm[(c + 1) * 136 + r + 8] = __float2half_rn(acc[mt][nt][3] * invT);
            }
        }
        __syncthreads();
        const int tr  = tid >> 1;
        const int seg = (tid & 1) << 6;
        const uint4* src = reinterpret_cast<const uint4*>(&Tsm[tr * 136 + seg]);
        uint4* dst = reinterpret_cast<uint4*>(&g_S[(size_t)(col0 + tr) * N + row0 + seg]);
#pragma unroll
        for (int k = 0; k < 8; k++) dst[k] = src[k];
    }
}

// ---------------- kernel 3: per-row loss, warp/row, prefetched S loads ------
__global__ void __launch_bounds__(256) k_rowloss(int N)
{
    const int tid  = threadIdx.x;
    const int lane = tid & 31;
    const int w    = tid >> 5;
    const int i    = blockIdx.x * 8 + w;

    const int b1 = g_bnd[1];
    const int b2 = g_bnd[2];
    const int NV = g_bnd[3];

    if (i >= NV) {
        if (lane == 0) { g_rowloss[i] = 0.f; g_rowflag[i] = 0; }
        return;
    }

    const int lo = (i < b1) ? 0  : ((i < b2) ? b1 : b2);
    const int hi = (i < b1) ? b1 : ((i < b2) ? b2 : NV);
    const int P  = hi - lo - 1;
    const int ntv = (NV + 127) >> 7;

    const uint4* __restrict__ rv = reinterpret_cast<const uint4*>(g_S + (size_t)i * N);
    const int v0 = lo >> 3;
    const int v1 = (hi + 7) >> 3;

    // prefetch first 2 S vectors per lane BEFORE the negpart latency chain
    uint4 pf[2];
    bool  hp[2] = {false, false};
    if (P > 0) {
#pragma unroll
        for (int p = 0; p < 2; p++) {
            const int vv = v0 + lane + 32 * p;
            hp[p] = vv < v1;
            if (hp[p]) pf[p] = rv[vv];
        }
    }

    // negsum from tile partials
    const float* __restrict__ np = g_negpart + (size_t)i * 64;
    float ns = (lane < ntv) ? np[lane] : 0.f;
    if (ntv > 32 && lane + 32 < ntv) ns += np[lane + 32];
    ns = wred_f(ns);
    const float L = (ns > 0.f) ? (__logf(ns) + 10.f) : -1e30f;

    if (L <= -1e29f) {
        if (lane == 0) { g_rowloss[i] = 0.f; g_rowflag[i] = 0; }
        return;
    }
    if (P == 0) {
        if (lane == 0) {
            g_rowloss[i] = softplus_fast(L - 10.f);
            g_rowflag[i] = 0;
        }
        return;
    }

    float psum = 0.f;
    // process prefetched vectors
#pragma unroll
    for (int p = 0; p < 2; p++) {
        if (!hp[p]) continue;
        const uint4 wv = pf[p];
        const int j0 = (v0 + lane + 32 * p) << 3;
        float s[8];
        {
            float2 f;
            f = __half22float2(*reinterpret_cast<const __half2*>(&wv.x)); s[0] = f.x; s[1] = f.y;
            f = __half22float2(*reinterpret_cast<const __half2*>(&wv.y)); s[2] = f.x; s[3] = f.y;
            f = __half22float2(*reinterpret_cast<const __half2*>(&wv.z)); s[4] = f.x; s[5] = f.y;
            f = __half22float2(*reinterpret_cast<const __half2*>(&wv.w)); s[6] = f.x; s[7] = f.y;
        }
        const bool interior = (j0 >= lo) && (j0 + 8 <= hi) &&
                              ((i < j0) || (i >= j0 + 8));
        if (interior) {
#pragma unroll
            for (int k = 0; k < 8; k++)
                psum += softplus_fast(L - s[k]);
        } else {
#pragma unroll
            for (int k = 0; k < 8; k++) {
                const int j = j0 + k;
                const bool m = (j >= lo) && (j < hi) && (j != i);
                psum += m ? softplus_fast(L - s[k]) : 0.f;
            }
        }
    }
    // remaining vectors
    for (int v = v0 + lane + 64; v < v1; v += 32) {
        uint4 wv = rv[v];
        const int j0 = v << 3;
        float s[8];
        {
            float2 f;
            f = __half22float2(*reinterpret_cast<__half2*>(&wv.x)); s[0] = f.x; s[1] = f.y;
            f = __half22float2(*reinterpret_cast<__half2*>(&wv.y)); s[2] = f.x; s[3] = f.y;
            f = __half22float2(*reinterpret_cast<__half2*>(&wv.z)); s[4] = f.x; s[5] = f.y;
            f = __half22float2(*reinterpret_cast<__half2*>(&wv.w)); s[6] = f.x; s[7] = f.y;
        }
        const bool interior = (j0 >= lo) && (j0 + 8 <= hi) &&
                              ((i < j0) || (i >= j0 + 8));
        if (interior) {
#pragma unroll
            for (int k = 0; k < 8; k++)
                psum += softplus_fast(L - s[k]);
        } else {
#pragma unroll
            for (int k = 0; k < 8; k++) {
                const int j = j0 + k;
                const bool m = (j >= lo) && (j < hi) && (j != i);
                psum += m ? softplus_fast(L - s[k]) : 0.f;
            }
        }
    }
    psum = wred_f(psum);
    if (lane == 0) {
        g_rowloss[i] = psum / (float)P;
        g_rowflag[i] = 1;
    }
}

// ---------------- kernel 4: final deterministic reduction (1024 thr) --------
__global__ void __launch_bounds__(1024) k_finalize(float* __restrict__ out, int N)
{
    const int tid = threadIdx.x;
    const float4* rl = reinterpret_cast<const float4*>(g_rowloss);
    const int4*   fl = reinterpret_cast<const int4*>(g_rowflag);
    float s = 0.f;
    int c = 0;
    for (int v = tid; v < N / 4; v += 1024) {
        float4 a = rl[v];
        int4   b = fl[v];
        s += a.x + a.y + a.z + a.w;
        c += b.x + b.y + b.z + b.w;
    }
    s = wred_f(s);
    c = wred_i(c);
    __shared__ float redf[32];
    __shared__ int   redi[32];
    if ((tid & 31) == 0) { redf[tid >> 5] = s; redi[tid >> 5] = c; }
    __syncthreads();
    if (tid == 0) {
        float tt = 0.f; int p = 0;
#pragma unroll
        for (int w = 0; w < 32; w++) { tt += redf[w]; p += redi[w]; }
        out[0] = tt / (float)(1 + p);
    }
}

// ---------------- launcher ---------------------------------------------------
extern "C" void kernel_launch(void* const* d_in, const int* in_sizes, int n_in,
                              void* d_out, int out_size)
{
    const float* feats  = (const float*)d_in[0];
    const int*   labels = (const int*)d_in[1];
    const int*   bad    = (const int*)d_in[2];
    float* out = (float*)d_out;

    const int N = in_sizes[1];            // 8192
    const int D = in_sizes[0] / N;        // 512

    cudaFuncSetAttribute(k_gemm_f16, cudaFuncAttributeMaxDynamicSharedMemorySize, SM_DYN);

    k_prep<<<1 + N / 32, 1024>>>(feats, labels, bad, N, D);

    const int ntiles = (NTILE * (NTILE + 1)) / 2;   // 2080 (most exit early)
    k_gemm_f16<<<ntiles, TCB, SM_DYN>>>(N, D);

    k_rowloss<<<N / 8, 256>>>(N);
    k_finalize<<<1, 1024>>>(out, N);
}

// round 17
// speedup vs baseline: 1.5334x; 1.5334x over previous
#include <cuda_runtime.h>
#include <cuda_fp16.h>
#include <math.h>
#include <stdint.h>

// Shapes fixed by the problem: N=8192, D=512, 3 classes
#define NMAX 8192
#define DMAX 512
#define NTILE 64   // N / 128

// ---------------- device scratch (static, no runtime allocation) ------------
__device__ __half g_fh[(size_t)NMAX * DMAX];   // normalized features, ORIGINAL order
__device__ __half g_S[(size_t)NMAX * NMAX];    // scaled logits (sorted coords), fp16
__device__ float  g_negpart[(size_t)NMAX * 64];// per-(sorted row, col-tile) exp partials
__device__ int    g_perm[NMAX];                // sorted -> original index
__device__ int    g_bnd[4];                    // {0, b1, b2, NV}
__device__ float  g_rowloss[NMAX];
__device__ int    g_rowflag[NMAX];

// ---------------- helpers ----------------------------------------------------
__device__ __forceinline__ float wred_f(float x) {
#pragma unroll
    for (int o = 16; o; o >>= 1) x += __shfl_xor_sync(0xffffffffu, x, o);
    return x;
}
__device__ __forceinline__ int wred_i(int x) {
#pragma unroll
    for (int o = 16; o; o >>= 1) x += __shfl_xor_sync(0xffffffffu, x, o);
    return x;
}
// softplus: exact 2-MUFU path for |d|<4, 1-MUFU quadratic for |d|>=4
__device__ __forceinline__ float softplus_fast(float d) {
    const float ad = fabsf(d);
    const float e  = __expf(-ad);
    const float base = fmaxf(d, 0.f);
    if (ad >= 4.f) {
        return base + e * (1.f - 0.5f * e);
    }
    return base + __logf(1.f + e);
}
__device__ __forceinline__ int clsof(int x, int b1, int b2, int NV) {
    return (x < b1) ? 0 : (x < b2) ? 1 : (x < NV) ? 2 : 3;
}

__device__ __forceinline__ void mma_f16(float* d, const uint32_t* a, const uint32_t* b) {
    asm volatile(
        "mma.sync.aligned.m16n8k16.row.col.f32.f16.f16.f32 "
        "{%0,%1,%2,%3}, {%4,%5,%6,%7}, {%8,%9}, {%0,%1,%2,%3};"
        : "+f"(d[0]), "+f"(d[1]), "+f"(d[2]), "+f"(d[3])
        : "r"(a[0]), "r"(a[1]), "r"(a[2]), "r"(a[3]),
          "r"(b[0]), "r"(b[1]));
}
__device__ __forceinline__ void ldsm_x4(uint32_t* r, uint32_t a) {
    asm volatile("ldmatrix.sync.aligned.m8n8.x4.shared.b16 {%0,%1,%2,%3}, [%4];"
                 : "=r"(r[0]), "=r"(r[1]), "=r"(r[2]), "=r"(r[3]) : "r"(a));
}
__device__ __forceinline__ void ldsm_x2(uint32_t* r, uint32_t a) {
    asm volatile("ldmatrix.sync.aligned.m8n8.x2.shared.b16 {%0,%1}, [%2];"
                 : "=r"(r[0]), "=r"(r[1]) : "r"(a));
}
__device__ __forceinline__ void cp_async16(uint32_t dst, const void* src) {
    size_t g = __cvta_generic_to_global(src);
    asm volatile("cp.async.cg.shared.global [%0], [%1], 16;"
                 :: "r"(dst), "l"(g) : "memory");
}

// ---------------- kernel 0: fused sort (block 0) + normalize (blocks 1..) ---
// Block 0: stable counting sort -> g_perm, g_bnd.
// Blocks 1..N/32: one WARP per row (4 float4 loads/lane = MLP 4, no syncs).
__global__ void __launch_bounds__(1024) k_prep(
    const float* __restrict__ feats,
    const int* __restrict__ labels,
    const int* __restrict__ bad,
    int N, int D)
{
    const int t = threadIdx.x;

    if (blockIdx.x == 0) {
        __shared__ uint32_t wt01[32], wt23[32];
        const int lane = t & 31;
        const int wid = t >> 5;

        const int4* lab4 = reinterpret_cast<const int4*>(labels);
        const int4* bad4 = reinterpret_cast<const int4*>(bad);
        int4 l0 = lab4[t * 2], l1 = lab4[t * 2 + 1];
        int4 d0 = bad4[t * 2], d1 = bad4[t * 2 + 1];

        int code[8];
        code[0] = (d0.x == 0) ? l0.x : 3;
        code[1] = (d0.y == 0) ? l0.y : 3;
        code[2] = (d0.z == 0) ? l0.z : 3;
        code[3] = (d0.w == 0) ? l0.w : 3;
        code[4] = (d1.x == 0) ? l1.x : 3;
        code[5] = (d1.y == 0) ? l1.y : 3;
        code[6] = (d1.z == 0) ? l1.z : 3;
        code[7] = (d1.w == 0) ? l1.w : 3;

        int cnt[4] = {0, 0, 0, 0};
#pragma unroll
        for (int e = 0; e < 8; e++) cnt[code[e]]++;

        uint32_t v01 = (uint32_t)cnt[0] | ((uint32_t)cnt[1] << 16);
        uint32_t v23 = (uint32_t)cnt[2] | ((uint32_t)cnt[3] << 16);
        uint32_t s01 = v01, s23 = v23;
#pragma unroll
        for (int off = 1; off < 32; off <<= 1) {
            uint32_t t1 = __shfl_up_sync(0xffffffffu, s01, off);
            uint32_t t2 = __shfl_up_sync(0xffffffffu, s23, off);
            if (lane >= off) { s01 += t1; s23 += t2; }
        }
        if (lane == 31) { wt01[wid] = s01; wt23[wid] = s23; }
        __syncthreads();
        if (wid == 0) {
            uint32_t w1 = wt01[lane], w2 = wt23[lane];
#pragma unroll
            for (int off = 1; off < 32; off <<= 1) {
                uint32_t t1 = __shfl_up_sync(0xffffffffu, w1, off);
                uint32_t t2 = __shfl_up_sync(0xffffffffu, w2, off);
                if (lane >= off) { w1 += t1; w2 += t2; }
            }
            wt01[lane] = w1; wt23[lane] = w2;
        }
        __syncthreads();

        const uint32_t wp01 = wid ? wt01[wid - 1] : 0u;
        const uint32_t wp23 = wid ? wt23[wid - 1] : 0u;
        const uint32_t tt01 = wt01[31], tt23 = wt23[31];

        const uint32_t ep01 = wp01 + s01 - v01;
        const uint32_t ep23 = wp23 + s23 - v23;
        int pre[4] = { (int)(ep01 & 0xffffu), (int)(ep01 >> 16),
                       (int)(ep23 & 0xffffu), (int)(ep23 >> 16) };
        const int tot0 = (int)(tt01 & 0xffffu);
        const int tot1 = (int)(tt01 >> 16);
        const int tot2 = (int)(tt23 & 0xffffu);
        int base[4] = { 0, tot0, tot0 + tot1, tot0 + tot1 + tot2 };

        int r[4] = {0, 0, 0, 0};
#pragma unroll
        for (int e = 0; e < 8; e++) {
            const int j = t * 8 + e;
            const int c = code[e];
            g_perm[base[c] + pre[c] + r[c]] = j;
            r[c]++;
        }
        if (t == 0) {
            g_bnd[0] = 0;
            g_bnd[1] = base[1];
            g_bnd[2] = base[2];
            g_bnd[3] = base[3];
        }
    } else {
        // normalize: one warp per row, 32 rows per block
        const int lane = t & 31;
        const int warp = t >> 5;
        const int row = (blockIdx.x - 1) * 32 + warp;

        const float4* src = reinterpret_cast<const float4*>(feats + (size_t)row * D);
        float4 v[4];
#pragma unroll
        for (int q = 0; q < 4; q++) v[q] = src[lane + 32 * q];

        float ss = 0.f;
#pragma unroll
        for (int q = 0; q < 4; q++)
            ss += v[q].x * v[q].x + v[q].y * v[q].y + v[q].z * v[q].z + v[q].w * v[q].w;
        ss = wred_f(ss);
        const float rinv = rsqrtf(ss);

        uint2* dst = reinterpret_cast<uint2*>(g_fh + (size_t)row * D);
#pragma unroll
        for (int q = 0; q < 4; q++) {
            uint2 o;
            __half2 h0 = __floats2half2_rn(v[q].x * rinv, v[q].y * rinv);
            __half2 h1 = __floats2half2_rn(v[q].z * rinv, v[q].w * rinv);
            o.x = *reinterpret_cast<uint32_t*>(&h0);
            o.y = *reinterpret_cast<uint32_t*>(&h1);
            dst[lane + 32 * q] = o;
        }
    }
}

// ---------------- kernel 2: fp16 GEMM, 128x128, 3-stage, perm-gathered ------
#define TCB 256
#define SM_STAGE 16384
#define SM_A(s) ((s) * SM_STAGE)
#define SM_B(s) (49152 + (s) * SM_STAGE)
#define SM_DYN 98304

__global__ void __launch_bounds__(TCB, 2) k_gemm_f16(int N, int D)
{
    extern __shared__ __align__(16) unsigned char dsm[];
    const uint32_t sbase = (uint32_t)__cvta_generic_to_shared(dsm);

    int t = blockIdx.x;
    int by = 0;
    {
        int rem = t;
        while (rem >= NTILE - by) { rem -= NTILE - by; by++; }
        t = rem;
    }
    const int bx = by + t;

    const int b1 = g_bnd[1];
    const int b2 = g_bnd[2];
    const int NV = g_bnd[3];
    const int ntv = (NV + 127) >> 7;
    if (bx >= ntv) return;

    const int row0 = by * 128;
    const int col0 = bx * 128;

    const int tid  = threadIdx.x;
    const int lane = tid & 31;
    const int warp = tid >> 5;
    const int wm   = warp >> 2;
    const int wn   = warp & 3;

    int cp_r[4], cp_sw[4], cp_g[4];
#pragma unroll
    for (int i = 0; i < 4; i++) {
        const int e = tid + i * TCB;
        cp_r[i]  = e >> 3;
        cp_g[i]  = e & 7;
        cp_sw[i] = cp_r[i] * 128 + ((cp_g[i] * 16) ^ ((cp_r[i] & 7) << 4));
    }

    const __half* __restrict__ fh = g_fh;
    const int* __restrict__ perm = g_perm;
    size_t prA[4], prB[4];
#pragma unroll
    for (int i = 0; i < 4; i++) {
        prA[i] = (size_t)perm[row0 + cp_r[i]] * D;
        prB[i] = (size_t)perm[col0 + cp_r[i]] * D;
    }

    float acc[4][4][4];
#pragma unroll
    for (int a = 0; a < 4; a++)
#pragma unroll
        for (int b = 0; b < 4; b++)
#pragma unroll
            for (int c = 0; c < 4; c++) acc[a][b][c] = 0.f;

    const int rr = lane & 7;
    const int xr = rr << 4;
    const int qa = lane >> 3;
    const int kA = (qa >> 1) << 4;
    const int kB = ((lane >> 3) & 1) << 4;
    int rowA[4], rowB[4];
#pragma unroll
    for (int mt = 0; mt < 4; mt++)
        rowA[mt] = ((wm << 6) + (mt << 4) + ((qa & 1) << 3) + rr) * 128;
#pragma unroll
    for (int nt = 0; nt < 4; nt++)
        rowB[nt] = ((wn << 5) + (nt << 3) + rr) * 128;

    const int NCH = D >> 6;

#pragma unroll
    for (int pc = 0; pc < 2; pc++) {
        const int koff = pc << 6;
#pragma unroll
        for (int i = 0; i < 4; i++) {
            cp_async16(sbase + SM_A(pc) + cp_sw[i], fh + prA[i] + koff + cp_g[i] * 8);
            cp_async16(sbase + SM_B(pc) + cp_sw[i], fh + prB[i] + koff + cp_g[i] * 8);
        }
        asm volatile("cp.async.commit_group;" ::: "memory");
    }

    for (int c = 0; c < NCH; c++) {
        const int buf = c % 3;
        if (c + 2 < NCH) {
            const int koff = (c + 2) << 6;
            const int nb = (c + 2) % 3;
#pragma unroll
            for (int i = 0; i < 4; i++) {
                cp_async16(sbase + SM_A(nb) + cp_sw[i], fh + prA[i] + koff + cp_g[i] * 8);
                cp_async16(sbase + SM_B(nb) + cp_sw[i], fh + prB[i] + koff + cp_g[i] * 8);
            }
            asm volatile("cp.async.commit_group;" ::: "memory");
            asm volatile("cp.async.wait_group 2;" ::: "memory");
        } else if (c + 1 < NCH) {
            asm volatile("cp.async.wait_group 1;" ::: "memory");
        } else {
            asm volatile("cp.async.wait_group 0;" ::: "memory");
        }
        __syncthreads();

        const uint32_t ab = sbase + SM_A(buf);
        const uint32_t bb = sbase + SM_B(buf);
#pragma unroll
        for (int ks = 0; ks < 4; ks++) {
            const int kk = ks << 5;
            uint32_t Af[4][4], Bf[4][2];
#pragma unroll
            for (int mt = 0; mt < 4; mt++)
                ldsm_x4(Af[mt], ab + rowA[mt] + ((kk + kA) ^ xr));
#pragma unroll
            for (int nt = 0; nt < 4; nt++)
                ldsm_x2(Bf[nt], bb + rowB[nt] + ((kk + kB) ^ xr));
#pragma unroll
            for (int mt = 0; mt < 4; mt++)
#pragma unroll
                for (int nt = 0; nt < 4; nt++)
                    mma_f16(acc[mt][nt], Af[mt], Bf[nt]);
        }
        __syncthreads();
    }

    // ---- epilogue ----
    float* SRow = reinterpret_cast<float*>(dsm);           // [128][4]
    float* SCol = reinterpret_cast<float*>(dsm + 2048);    // [128][2]
    __half* Tsm = reinterpret_cast<__half*>(dsm);          // reuse

    const float invT = 10.f;
    const int g  = lane >> 2;
    const int tq = lane & 3;

    bool storeT;
    {
        const int r0 = row0, r1 = row0 + 128, c0 = col0, c1 = col0 + 128;
        storeT = (r0 < b1 && c0 < b1)
              || (r0 < b2 && r1 > b1 && c0 < b2 && c1 > b1)
              || (r1 > b2 && c1 > b2 && row0 < NV && col0 < NV);
    }
    const bool allsame =
        (clsof(row0, b1, b2, NV) == clsof(row0 + 127, b1, b2, NV)) &&
        (clsof(col0, b1, b2, NV) == clsof(col0 + 127, b1, b2, NV)) &&
        (clsof(row0, b1, b2, NV) == clsof(col0, b1, b2, NV)) &&
        (clsof(row0, b1, b2, NV) != 3);

    if (storeT) {
        __half* __restrict__ S = g_S;
#pragma unroll
        for (int mt = 0; mt < 4; mt++) {
            const int row = row0 + (wm << 6) + (mt << 4) + g;
#pragma unroll
            for (int nt = 0; nt < 4; nt++) {
                const int col = col0 + (wn << 5) + (nt << 3) + (tq << 1);
                __half2 lo = __floats2half2_rn(acc[mt][nt][0] * invT, acc[mt][nt][1] * invT);
                __half2 hi = __floats2half2_rn(acc[mt][nt][2] * invT, acc[mt][nt][3] * invT);
                *reinterpret_cast<__half2*>(&S[(size_t)row * N + col]) = lo;
                *reinterpret_cast<__half2*>(&S[(size_t)(row + 8) * N + col]) = hi;
            }
        }
    }

    float rsum[8] = {0, 0, 0, 0, 0, 0, 0, 0};
    float csum[8] = {0, 0, 0, 0, 0, 0, 0, 0};
    if (!allsame) {
        int rcls[8], ccls[8];
#pragma unroll
        for (int mt = 0; mt < 4; mt++)
#pragma unroll
            for (int h = 0; h < 2; h++) {
                const int r = row0 + (wm << 6) + (mt << 4) + g + 8 * h;
                rcls[mt * 2 + h] = clsof(r, b1, b2, NV);
            }
#pragma unroll
        for (int nt = 0; nt < 4; nt++)
#pragma unroll
            for (int c = 0; c < 2; c++) {
                const int cc = col0 + (wn << 5) + (nt << 3) + (tq << 1) + c;
                ccls[nt * 2 + c] = clsof(cc, b1, b2, NV);
            }
#pragma unroll
        for (int mt = 0; mt < 4; mt++)
#pragma unroll
            for (int h = 0; h < 2; h++) {
                const int rc = rcls[mt * 2 + h];
#pragma unroll
                for (int nt = 0; nt < 4; nt++)
#pragma unroll
                    for (int c = 0; c < 2; c++) {
                        const int cc = ccls[nt * 2 + c];
                        const float s = acc[mt][nt][2 * h + c] * invT;
                        const float e = __expf(s - 10.f);
                        const bool m = (rc != cc) && (rc != 3) && (cc != 3);
                        const float ev = m ? e : 0.f;
                        rsum[mt * 2 + h] += ev;
                        csum[nt * 2 + c] += ev;
                    }
            }
#pragma unroll
        for (int k = 0; k < 8; k++) {
            rsum[k] += __shfl_xor_sync(0xffffffffu, rsum[k], 1);
            rsum[k] += __shfl_xor_sync(0xffffffffu, rsum[k], 2);
            csum[k] += __shfl_xor_sync(0xffffffffu, csum[k], 4);
            csum[k] += __shfl_xor_sync(0xffffffffu, csum[k], 8);
            csum[k] += __shfl_xor_sync(0xffffffffu, csum[k], 16);
        }
    }
    if (tq == 0) {
#pragma unroll
        for (int mt = 0; mt < 4; mt++)
#pragma unroll
            for (int h = 0; h < 2; h++) {
                const int rl = (wm << 6) + (mt << 4) + g + 8 * h;
                SRow[rl * 4 + wn] = rsum[mt * 2 + h];
            }
    }
    if (g == 0) {
#pragma unroll
        for (int nt = 0; nt < 4; nt++)
#pragma unroll
            for (int c = 0; c < 2; c++) {
                const int cl = (wn << 5) + (nt << 3) + (tq << 1) + c;
                SCol[cl * 2 + wm] = csum[nt * 2 + c];
            }
    }
    __syncthreads();

    if (tid < 128) {
        const float rp = SRow[tid * 4 + 0] + SRow[tid * 4 + 1]
                       + SRow[tid * 4 + 2] + SRow[tid * 4 + 3];
        g_negpart[(size_t)(row0 + tid) * 64 + bx] = rp;
    } else if (bx != by) {
        const int c = tid - 128;
        const float cp = SCol[c * 2 + 0] + SCol[c * 2 + 1];
        g_negpart[(size_t)(col0 + c) * 64 + by] = cp;
    }

    if (storeT && bx != by) {
        __syncthreads();
#pragma unroll
        for (int mt = 0; mt < 4; mt++) {
            const int r = (wm << 6) + (mt << 4) + g;
#pragma unroll
            for (int nt = 0; nt < 4; nt++) {
                const int c = (wn << 5) + (nt << 3) + (tq << 1);
                Tsm[(c) * 136 + r]         = __float2half_rn(acc[mt][nt][0] * invT);
                Tsm[(c + 1) * 136 + r]     = __float2half_rn(acc[mt][nt][1] * invT);
                Tsm[(c) * 136 + r + 8]     = __float2half_rn(acc[mt][nt][2] * invT);
                Tsm[(c + 1) * 136 + r + 8] = __float2half_rn(acc[mt][nt][3] * invT);
            }
        }
        __syncthreads();
        const int tr  = tid >> 1;
        const int seg = (tid & 1) << 6;
        const uint4* src = reinterpret_cast<const uint4*>(&Tsm[tr * 136 + seg]);
        uint4* dst = reinterpret_cast<uint4*>(&g_S[(size_t)(col0 + tr) * N + row0 + seg]);
#pragma unroll
        for (int k = 0; k < 8; k++) dst[k] = src[k];
    }
}

// ---------------- kernel 3: per-row loss, ONE WARP PER ROW (R14 version) ----
__global__ void __launch_bounds__(256) k_rowloss(int N)
{
    const int tid  = threadIdx.x;
    const int lane = tid & 31;
    const int w    = tid >> 5;
    const int i    = blockIdx.x * 8 + w;

    const int b1 = g_bnd[1];
    const int b2 = g_bnd[2];
    const int NV = g_bnd[3];

    if (i >= NV) {
        if (lane == 0) { g_rowloss[i] = 0.f; g_rowflag[i] = 0; }
        return;
    }

    const int lo = (i < b1) ? 0  : ((i < b2) ? b1 : b2);
    const int hi = (i < b1) ? b1 : ((i < b2) ? b2 : NV);
    const int P  = hi - lo - 1;
    const int ntv = (NV + 127) >> 7;

    const float* __restrict__ np = g_negpart + (size_t)i * 64;
    float ns = (lane < ntv) ? np[lane] : 0.f;
    if (ntv > 32 && lane + 32 < ntv) ns += np[lane + 32];
    ns = wred_f(ns);
    const float L = (ns > 0.f) ? (__logf(ns) + 10.f) : -1e30f;

    if (L <= -1e29f) {
        if (lane == 0) { g_rowloss[i] = 0.f; g_rowflag[i] = 0; }
        return;
    }
    if (P == 0) {
        if (lane == 0) {
            g_rowloss[i] = softplus_fast(L - 10.f);
            g_rowflag[i] = 0;
        }
        return;
    }

    const uint4* __restrict__ rv = reinterpret_cast<const uint4*>(g_S + (size_t)i * N);

    float psum = 0.f;
    const int v0 = lo >> 3;
    const int v1 = (hi + 7) >> 3;
    for (int v = v0 + lane; v < v1; v += 32) {
        uint4 wv = rv[v];
        const int j0 = v << 3;
        float s[8];
        {
            float2 f;
            f = __half22float2(*reinterpret_cast<__half2*>(&wv.x)); s[0] = f.x; s[1] = f.y;
            f = __half22float2(*reinterpret_cast<__half2*>(&wv.y)); s[2] = f.x; s[3] = f.y;
            f = __half22float2(*reinterpret_cast<__half2*>(&wv.z)); s[4] = f.x; s[5] = f.y;
            f = __half22float2(*reinterpret_cast<__half2*>(&wv.w)); s[6] = f.x; s[7] = f.y;
        }
        const bool interior = (j0 >= lo) && (j0 + 8 <= hi) &&
                              ((i < j0) || (i >= j0 + 8));
        if (interior) {
#pragma unroll
            for (int k = 0; k < 8; k++)
                psum += softplus_fast(L - s[k]);
        } else {
#pragma unroll
            for (int k = 0; k < 8; k++) {
                const int j = j0 + k;
                const bool m = (j >= lo) && (j < hi) && (j != i);
                psum += m ? softplus_fast(L - s[k]) : 0.f;
            }
        }
    }
    psum = wred_f(psum);
    if (lane == 0) {
        g_rowloss[i] = psum / (float)P;
        g_rowflag[i] = 1;
    }
}

// ---------------- kernel 4: final deterministic reduction (1024 thr) --------
__global__ void __launch_bounds__(1024) k_finalize(float* __restrict__ out, int N)
{
    const int tid = threadIdx.x;
    const float4* rl = reinterpret_cast<const float4*>(g_rowloss);
    const int4*   fl = reinterpret_cast<const int4*>(g_rowflag);
    float s = 0.f;
    int c = 0;
    for (int v = tid; v < N / 4; v += 1024) {
        float4 a = rl[v];
        int4   b = fl[v];
        s += a.x + a.y + a.z + a.w;
        c += b.x + b.y + b.z + b.w;
    }
    s = wred_f(s);
    c = wred_i(c);
    __shared__ float redf[32];
    __shared__ int   redi[32];
    if ((tid & 31) == 0) { redf[tid >> 5] = s; redi[tid >> 5] = c; }
    __syncthreads();
    if (tid == 0) {
        float tt = 0.f; int p = 0;
#pragma unroll
        for (int w = 0; w < 32; w++) { tt += redf[w]; p += redi[w]; }
        out[0] = tt / (float)(1 + p);
    }
}

// ---------------- launcher ---------------------------------------------------
extern "C" void kernel_launch(void* const* d_in, const int* in_sizes, int n_in,
                              void* d_out, int out_size)
{
    const float* feats  = (const float*)d_in[0];
    const int*   labels = (const int*)d_in[1];
    const int*   bad    = (const int*)d_in[2];
    float* out = (float*)d_out;

    const int N = in_sizes[1];            // 8192
    const int D = in_sizes[0] / N;        // 512

    cudaFuncSetAttribute(k_gemm_f16, cudaFuncAttributeMaxDynamicSharedMemorySize, SM_DYN);

    k_prep<<<1 + N / 32, 1024>>>(feats, labels, bad, N, D);

    const int ntiles = (NTILE * (NTILE + 1)) / 2;   // 2080 (most exit early)
    k_gemm_f16<<<ntiles, TCB, SM_DYN>>>(N, D);

    k_rowloss<<<N / 8, 256>>>(N);
    k_finalize<<<1, 1024>>>(out, N);
}